// round 8
// baseline (speedup 1.0000x reference)
#include <cuda_runtime.h>

// Fused Bayer demosaic. Quadrant -> (R,G,B) stencil map:
//   q0 (i even, j even): (diag, plus, center)
//   q1 (i even, j odd ): (vavg, center, havg)
//   q2 (i odd , j even): (havg, center, vavg)
//   q3 (i odd , j odd ): (center, plus, diag)
//
// R6 = R5 with the smem row stride fixed to a 16-byte multiple
// (TILE+4 = 1028 floats = 4112 B) so float4 STS/LDS stay aligned.
// Each thread: 3 independent float4 LDGs (max MLP, zero halo LDGs),
// stage to smem, one barrier, read 6-wide windows via LDS.

#define TILE 1024     // 256 threads * 4 px
#define SROW (TILE + 4)  // halos at [TILE], [TILE+1]; +2 pad for 16B stride

__global__ __launch_bounds__(256) void bayer_demosaic_kernel(
    const float* __restrict__ x, float* __restrict__ y, int H, int W) {
    __shared__ float s[3][SROW];

    const int t4 = threadIdx.x * 4;
    const int bs = blockIdx.x * TILE;
    const int i  = blockIdx.y;
    const int n  = blockIdx.z;

    const size_t plane = (size_t)H * W;
    const float* xp = x + (size_t)n * plane;

    const int im1 = (i == 0)     ? 1     : i - 1;   // reflect rows
    const int ip1 = (i == H - 1) ? H - 2 : i + 1;

    const float* rp0 = xp + (size_t)im1 * W;  // row above
    const float* rp1 = xp + (size_t)i   * W;  // center row
    const float* rp2 = xp + (size_t)ip1 * W;  // row below

    // 3 independent vector loads -> smem (aligned STS.128)
    const float4 m0 = *reinterpret_cast<const float4*>(rp0 + bs + t4);
    const float4 m1 = *reinterpret_cast<const float4*>(rp1 + bs + t4);
    const float4 m2 = *reinterpret_cast<const float4*>(rp2 + bs + t4);
    *reinterpret_cast<float4*>(&s[0][t4]) = m0;
    *reinterpret_cast<float4*>(&s[1][t4]) = m1;
    *reinterpret_cast<float4*>(&s[2][t4]) = m2;

    // halo columns: logical col bs-1 (reflect -1 -> 1) and bs+TILE (reflect W -> W-2)
    if (threadIdx.x < 3) {
        const float* rp = (threadIdx.x == 0) ? rp0 : (threadIdx.x == 1) ? rp1 : rp2;
        s[threadIdx.x][TILE] = (bs == 0) ? rp[1] : rp[bs - 1];
    } else if (threadIdx.x >= 253) {
        const int r = threadIdx.x - 253;
        const float* rp = (r == 0) ? rp0 : (r == 1) ? rp1 : rp2;
        s[r][TILE + 1] = (bs + TILE >= W) ? rp[W - 2] : rp[bs + TILE];
    }
    __syncthreads();

    // 6-wide windows from smem
    const int idxL = (t4 == 0)        ? TILE     : t4 - 1;
    const int idxR = (t4 == TILE - 4) ? TILE + 1 : t4 + 4;

    float a[6], b[6], c[6];
    {
        const float4 w0 = *reinterpret_cast<const float4*>(&s[0][t4]);
        a[1] = w0.x; a[2] = w0.y; a[3] = w0.z; a[4] = w0.w;
        a[0] = s[0][idxL]; a[5] = s[0][idxR];
        const float4 w1 = *reinterpret_cast<const float4*>(&s[1][t4]);
        b[1] = w1.x; b[2] = w1.y; b[3] = w1.z; b[4] = w1.w;
        b[0] = s[1][idxL]; b[5] = s[1][idxR];
        const float4 w2 = *reinterpret_cast<const float4*>(&s[2][t4]);
        c[1] = w2.x; c[2] = w2.y; c[3] = w2.z; c[4] = w2.w;
        c[0] = s[2][idxL]; c[5] = s[2][idxR];
    }

    float R[4], G[4], B[4];
    const int ip = i & 1;
#pragma unroll
    for (int t = 0; t < 4; ++t) {
        const float center = b[t + 1];
        const float plus   = 0.25f * ((a[t + 1] + c[t + 1]) + (b[t] + b[t + 2]));
        const float diag   = 0.25f * ((a[t] + a[t + 2]) + (c[t] + c[t + 2]));
        const float havg   = 0.5f  * (b[t] + b[t + 2]);
        const float vavg   = 0.5f  * (a[t + 1] + c[t + 1]);
        const int jp = t & 1;  // col = bs + t4 + t; bs + t4 is a multiple of 4
        if (ip == 0) {
            if (jp == 0) { R[t] = diag;   G[t] = plus;   B[t] = center; }  // q0
            else         { R[t] = vavg;   G[t] = center; B[t] = havg;   }  // q1
        } else {
            if (jp == 0) { R[t] = havg;   G[t] = center; B[t] = vavg;   }  // q2
            else         { R[t] = center; G[t] = plus;   B[t] = diag;   }  // q3
        }
    }

    float* yn = y + (size_t)n * 3 * plane + (size_t)i * W + bs + t4;
    *reinterpret_cast<float4*>(yn)             = make_float4(R[0], R[1], R[2], R[3]);
    *reinterpret_cast<float4*>(yn + plane)     = make_float4(G[0], G[1], G[2], G[3]);
    *reinterpret_cast<float4*>(yn + 2 * plane) = make_float4(B[0], B[1], B[2], B[3]);
}

extern "C" void kernel_launch(void* const* d_in, const int* in_sizes, int n_in,
                              void* d_out, int out_size) {
    const float* x = (const float*)d_in[0];
    float* y = (float*)d_out;

    const int H = 4096, W = 4096;
    const int N = in_sizes[0] / (H * W);  // = 2

    dim3 block(256, 1, 1);
    dim3 grid(W / TILE, H, N);
    bayer_demosaic_kernel<<<grid, block>>>(x, y, H, W);
}

// round 10
// speedup vs baseline: 1.0953x; 1.0953x over previous
#include <cuda_runtime.h>

// Fused Bayer demosaic, rolling vertical stencil.
// Quadrant -> (R,G,B) stencil map:
//   q0 (i even, j even): (diag, plus, center)
//   q1 (i even, j odd ): (vavg, center, havg)
//   q2 (i odd , j even): (havg, center, vavg)
//   q3 (i odd , j odd ): (center, plus, diag)
//
// R8: each block owns a 1024-wide x 8-row strip. Registers carry rows
// (a,b,c); each iteration preloads row i+2 (independent of current compute),
// computes+stores row i, rotates. 1 vector load + 2 halo scalars per row
// instead of 3+6. Row parity is compile-time (unrolled loop).

#define RROWS 8

__device__ __forceinline__ void load_row6(const float* __restrict__ r,
                                          int j0, int W, bool fast,
                                          float v[6]) {
    if (fast) {
        float4 m = *reinterpret_cast<const float4*>(r + j0);
        v[0] = __ldg(r + j0 - 1);
        v[1] = m.x; v[2] = m.y; v[3] = m.z; v[4] = m.w;
        v[5] = __ldg(r + j0 + 4);
    } else {
#pragma unroll
        for (int k = 0; k < 6; ++k) {
            int c = j0 + k - 1;
            c = (c < 0) ? -c : c;                 // reflect: -1 -> 1
            c = (c >= W) ? (2 * W - 2 - c) : c;   // reflect: W -> W-2
            v[k] = __ldg(r + c);
        }
    }
}

__global__ __launch_bounds__(256) void bayer_demosaic_kernel(
    const float* __restrict__ x, float* __restrict__ y, int H, int W) {
    const int j0 = blockIdx.x * 1024 + threadIdx.x * 4;
    const int i0 = blockIdx.y * RROWS;
    const int n  = blockIdx.z;

    const size_t plane = (size_t)H * W;
    const float* xp = x + (size_t)n * plane;
    float* yp = y + (size_t)n * 3 * plane;

    const bool fast = (j0 > 0) && (j0 + 4 < W);

    float a[6], b[6], c[6];
    {
        const int im1 = (i0 == 0) ? 1 : i0 - 1;     // reflect row -1 -> 1
        load_row6(xp + (size_t)im1 * W,      j0, W, fast, a);
        load_row6(xp + (size_t)i0 * W,       j0, W, fast, b);
        load_row6(xp + (size_t)(i0 + 1) * W, j0, W, fast, c);  // i0+1 <= H-7 < H
    }

#pragma unroll
    for (int t = 0; t < RROWS; ++t) {
        const int i = i0 + t;

        // Preload row i+2 (reflected at the bottom edge) BEFORE computing
        // row i, so the DRAM miss overlaps this row's math + stores.
        float nx[6];
        {
            int rn = i + 2;
            rn = (rn >= H) ? 2 * H - 2 - rn : rn;   // reflect H -> H-2 (H+1 preload unused but safe)
            load_row6(xp + (size_t)rn * W, j0, W, fast, nx);
        }

        float R[4], G[4], B[4];
#pragma unroll
        for (int s = 0; s < 4; ++s) {
            const float center = b[s + 1];
            const float plus   = 0.25f * ((a[s + 1] + c[s + 1]) + (b[s] + b[s + 2]));
            const float diag   = 0.25f * ((a[s] + a[s + 2]) + (c[s] + c[s + 2]));
            const float havg   = 0.5f  * (b[s] + b[s + 2]);
            const float vavg   = 0.5f  * (a[s + 1] + c[s + 1]);
            // i0 multiple of 8, j0 multiple of 4 -> both parities compile-time
            if ((t & 1) == 0) {
                if ((s & 1) == 0) { R[s] = diag;   G[s] = plus;   B[s] = center; }  // q0
                else              { R[s] = vavg;   G[s] = center; B[s] = havg;   }  // q1
            } else {
                if ((s & 1) == 0) { R[s] = havg;   G[s] = center; B[s] = vavg;   }  // q2
                else              { R[s] = center; G[s] = plus;   B[s] = diag;   }  // q3
            }
        }

        float* yn = yp + (size_t)i * W + j0;
        *reinterpret_cast<float4*>(yn)             = make_float4(R[0], R[1], R[2], R[3]);
        *reinterpret_cast<float4*>(yn + plane)     = make_float4(G[0], G[1], G[2], G[3]);
        *reinterpret_cast<float4*>(yn + 2 * plane) = make_float4(B[0], B[1], B[2], B[3]);

        // rotate rows (register renaming after full unroll)
#pragma unroll
        for (int k = 0; k < 6; ++k) { a[k] = b[k]; b[k] = c[k]; c[k] = nx[k]; }
    }
}

extern "C" void kernel_launch(void* const* d_in, const int* in_sizes, int n_in,
                              void* d_out, int out_size) {
    const float* x = (const float*)d_in[0];
    float* y = (float*)d_out;

    const int H = 4096, W = 4096;
    const int N = in_sizes[0] / (H * W);  // = 2

    dim3 block(256, 1, 1);
    dim3 grid(W / 1024, H / RROWS, N);
    bayer_demosaic_kernel<<<grid, block>>>(x, y, H, W);
}